// round 11
// baseline (speedup 1.0000x reference)
#include <cuda_runtime.h>
#include <cuda_fp16.h>
#include <cstdint>
#include <math.h>

// ---------------- problem constants ----------------
#define Bdim 2
#define Nn   2048
#define Ff   64
#define Cc   64
#define Ll   4
#define Kk   (Nn*Ll)            // 8192
#define BM 64                   // rows per block (4 CTA/SM)
#define BKH 64                  // fp16 k-elements per tile (128 B rows)
#define NKTILES (Kk/BKH)        // 128
#define SPLITK 9                // 32 mtiles*2*9 = 576 blocks = 1 wave @ 4 CTA/SM

// ---------------- scratch (static device globals) ----------------
__device__ __align__(16) __half g_W3VTh[(size_t)Bdim*Cc*Kk];     // [b][c][k] fp16
__device__ __align__(16) float g_W2V [(size_t)Bdim*Nn*Ll*Cc];    // [m][l*64+c]
__device__ __align__(16) float g_accum[(size_t)Bdim*Nn*Cc];      // T1 - term3 (atomic)
__device__ __align__(16) float g_deg [(size_t)Bdim*Nn*Ll];       // deg (atomic)
__device__ unsigned int g_cnt[64];                               // split-K arrival counters

// ---------------- helpers ----------------
__device__ __forceinline__ uint32_t smem_u32(const void* p) {
    uint32_t a;
    asm("{ .reg .u64 t; cvta.to.shared.u64 t, %1; cvt.u32.u64 %0, t; }" : "=r"(a) : "l"(p));
    return a;
}
__device__ __forceinline__ float to_tf32(float x) {
    uint32_t u;
    asm("cvt.rna.tf32.f32 %0, %1;" : "=r"(u) : "f"(x));
    return __uint_as_float(u);
}
__device__ __forceinline__ uint32_t sw128(uint32_t off) { return off ^ ((off >> 3) & 0x70); }
__device__ __forceinline__ uint32_t f22h2(float x, float y) {
    __half2 h = __floats2half2_rn(x, y);
    return *(uint32_t*)&h;
}

#define CP16(dst, src) \
    asm volatile("cp.async.cg.shared.global [%0], [%1], 16;" \
        :: "r"(dst), "l"(__cvta_generic_to_global(src)) : "memory")
#define CPCOMMIT() asm volatile("cp.async.commit_group;" ::: "memory")
#define CPWAIT(n)  asm volatile("cp.async.wait_group %0;" :: "n"(n) : "memory")

#define RED2(addr, x, y) \
    asm volatile("red.global.add.v2.f32 [%0], {%1, %2};" \
        :: "l"(addr), "f"(x), "f"(y) : "memory")

#define LDSM_X4(r, addr)                                                         \
    asm volatile("ldmatrix.sync.aligned.m8n8.x4.shared.b16 {%0,%1,%2,%3}, [%4];" \
        : "=r"((r)[0]), "=r"((r)[1]), "=r"((r)[2]), "=r"((r)[3]) : "r"(addr))

#define MMA_TF32(c, a, b0v, b1v)                                                 \
    asm volatile("mma.sync.aligned.m16n8k8.row.col.f32.tf32.tf32.f32 "           \
        "{%0,%1,%2,%3}, {%4,%5,%6,%7}, {%8,%9}, {%0,%1,%2,%3};"                  \
        : "+f"((c)[0]), "+f"((c)[1]), "+f"((c)[2]), "+f"((c)[3])                  \
        : "r"((a)[0]), "r"((a)[1]), "r"((a)[2]), "r"((a)[3]), "r"(b0v), "r"(b1v))

#define MMA_F16(c, a, b0v, b1v)                                                  \
    asm volatile("mma.sync.aligned.m16n8k16.row.col.f32.f16.f16.f32 "            \
        "{%0,%1,%2,%3}, {%4,%5,%6,%7}, {%8,%9}, {%0,%1,%2,%3};"                  \
        : "+f"((c)[0]), "+f"((c)[1]), "+f"((c)[2]), "+f"((c)[3])                  \
        : "r"((a)[0]), "r"((a)[1]), "r"((a)[2]), "r"((a)[3]), "r"(b0v), "r"(b1v))

// ---------------- precompute GEMM (tf32x3): [W3V | W2V | T1->accum] = V @ Wcat ----------------
// grid (32 M-tiles of 128 rows, 9 N-chunks), 256 threads.
// Weights loaded directly (transpose + tf32 split on the fly); nc==4 blocks
// also zero g_deg and g_cnt for this replay.
__global__ __launch_bounds__(256)
void pregemm_kernel(const float* __restrict__ V,
                    const float* __restrict__ w1,
                    const float* __restrict__ w2,
                    const float* __restrict__ w3) {
    __shared__ __align__(128) float sAhi[128 * 32];
    __shared__ __align__(128) float sAlo[128 * 32];
    __shared__ __align__(128) float sBhi[64 * 32];
    __shared__ __align__(128) float sBlo[64 * 32];
    const uint32_t aH = smem_u32(sAhi), aL = smem_u32(sAlo);
    const uint32_t bH = smem_u32(sBhi), bL = smem_u32(sBlo);

    const int mtile = blockIdx.x, nc = blockIdx.y;
    const int m0 = mtile * 128;
    const int tid = threadIdx.x, wid = tid >> 5, lid = tid & 31;
    const int wm = wid & 3, wn = wid >> 2;

    // per-replay scratch reset (runs before gemm launch; kernel-boundary ordered)
    if (nc == 4) {
        float2 z; z.x = 0.f; z.y = 0.f;
        *(float2*)(g_deg + (size_t)mtile * 512 + tid * 2) = z;   // 32*512 = 16384
        if (mtile == 0 && tid < 64) g_cnt[tid] = 0u;
    }

    const float* Ab = V + (size_t)m0 * Ff;

    const int q = lid >> 3, rr = lid & 7;
    uint32_t aOff[2], bOff[2];
#pragma unroll
    for (int mt = 0; mt < 2; mt++)
        aOff[mt] = (uint32_t)((wm * 32 + mt * 16 + rr + (q & 1) * 8) * 128 + (q >> 1) * 16);
#pragma unroll
    for (int h = 0; h < 2; h++)
        bOff[h]  = (uint32_t)((wn * 32 + h * 16 + rr + (q >> 1) * 8) * 128 + (q & 1) * 16);

    float acc[2][4][4];
#pragma unroll
    for (int mt = 0; mt < 2; mt++)
#pragma unroll
        for (int nt = 0; nt < 4; nt++)
#pragma unroll
            for (int e = 0; e < 4; e++) acc[mt][nt][e] = 0.f;

    for (int kt = 0; kt < 2; kt++) {
        // stage A (hi/lo split)
#pragma unroll
        for (int it = 0; it < 4; it++) {
            const int idx = it * 256 + tid, row = idx >> 3, f4 = idx & 7;
            const float4 v = *(const float4*)(Ab + (size_t)row * Ff + kt * 32 + f4 * 4);
            float4 h, l;
            h.x = to_tf32(v.x); l.x = to_tf32(v.x - h.x);
            h.y = to_tf32(v.y); l.y = to_tf32(v.y - h.y);
            h.z = to_tf32(v.z); l.z = to_tf32(v.z - h.z);
            h.w = to_tf32(v.w); l.w = to_tf32(v.w - h.w);
            const uint32_t off = sw128((uint32_t)(row * 128 + f4 * 16));
            *(float4*)((char*)sAhi + off) = h;
            *(float4*)((char*)sAlo + off) = l;
        }
        // stage B: Wcat^T[nc*64+row][k] loaded directly from w1/w2/w3, split hi/lo
#pragma unroll
        for (int it = 0; it < 2; it++) {
            const int idx = it * 256 + tid, row = idx >> 3, f4 = idx & 7;
            const int t = nc * 64 + row;
            float4 v;
#pragma unroll
            for (int e = 0; e < 4; e++) {
                const int f = kt * 32 + f4 * 4 + e;
                float val;
                if (t < 256)      val = w3[((t >> 6) * Ff + f) * Cc + (t & 63)];
                else if (t < 512) val = w2[(((t - 256) >> 6) * Ff + f) * Cc + ((t - 256) & 63)];
                else              val = w1[f * Cc + (t - 512)];
                ((float*)&v)[e] = val;
            }
            float4 h, l;
            h.x = to_tf32(v.x); l.x = to_tf32(v.x - h.x);
            h.y = to_tf32(v.y); l.y = to_tf32(v.y - h.y);
            h.z = to_tf32(v.z); l.z = to_tf32(v.z - h.z);
            h.w = to_tf32(v.w); l.w = to_tf32(v.w - h.w);
            const uint32_t off = sw128((uint32_t)(row * 128 + f4 * 16));
            *(float4*)((char*)sBhi + off) = h;
            *(float4*)((char*)sBlo + off) = l;
        }
        __syncthreads();

#pragma unroll
        for (int ks = 0; ks < 4; ks++) {
            uint32_t afh[2][4], afl[2][4], bfh[2][4], bfl[2][4];
#pragma unroll
            for (int mt = 0; mt < 2; mt++) {
                uint32_t o = aOff[mt] + ks * 32, so = (o ^ ((o >> 3) & 0x70));
                LDSM_X4(afh[mt], aH + so);
                LDSM_X4(afl[mt], aL + so);
            }
#pragma unroll
            for (int h = 0; h < 2; h++) {
                uint32_t o = bOff[h] + ks * 32, so = (o ^ ((o >> 3) & 0x70));
                LDSM_X4(bfh[h], bH + so);
                LDSM_X4(bfl[h], bL + so);
            }
#pragma unroll
            for (int mt = 0; mt < 2; mt++)
#pragma unroll
                for (int nt = 0; nt < 4; nt++) {
                    const int hb = nt >> 1, eb = (nt & 1) * 2;
                    MMA_TF32(acc[mt][nt], afl[mt], bfh[hb][eb], bfh[hb][eb + 1]);
                    MMA_TF32(acc[mt][nt], afh[mt], bfl[hb][eb], bfl[hb][eb + 1]);
                    MMA_TF32(acc[mt][nt], afh[mt], bfh[hb][eb], bfh[hb][eb + 1]);
                }
        }
        __syncthreads();
    }

    const int gid = lid >> 2, tig = lid & 3;
#pragma unroll
    for (int mt = 0; mt < 2; mt++)
#pragma unroll
        for (int nt = 0; nt < 4; nt++)
#pragma unroll
            for (int e = 0; e < 4; e++) {
                const int row = wm * 32 + mt * 16 + gid + (e >> 1) * 8;
                const int col = wn * 32 + nt * 8 + 2 * tig + (e & 1);
                const int m = m0 + row;
                const float v = acc[mt][nt][e];
                if (nc < 4) {
                    const int bb = m >> 11, j = m & 2047;
                    g_W3VTh[((size_t)(bb * 64 + col)) * Kk + j * 4 + nc] = __float2half_rn(v);
                } else if (nc < 8) {
                    g_W2V[(size_t)m * 256 + (nc - 4) * 64 + col] = v;
                } else {
                    g_accum[(size_t)m * 64 + col] = v;   // T1 seeds the accumulator
                }
            }
}

// ---------------- main GEMM: fp16 m16n8k16 + fused split-K finisher ----------------
// grid (32, Bdim, SPLITK) = 576 blocks, 256 threads (8 warps).
// The 9th-arriving split per (mtb,b) tile finalizes its 64 rows: sigmoid(accum + deg.W2V).
__global__ __launch_bounds__(256, 4)
void gemm_kernel(const float* __restrict__ A, float* __restrict__ out) {
    __shared__ __align__(128) uint8_t smemRaw[32768];  // A:2x8KB, B:2x8KB
    __shared__ unsigned int sLast;
    const uint32_t sm = smem_u32(smemRaw);
    const uint32_t sAu[2] = { sm, sm + 8192 };
    const uint32_t sBu[2] = { sm + 16384, sm + 24576 };

    const int mtb = blockIdx.x, b = blockIdx.y, s = blockIdx.z;
    const int i0 = mtb * BM;
    const int t0 = (s * NKTILES) / SPLITK, t1 = ((s + 1) * NKTILES) / SPLITK;
    const int nkt = t1 - t0;
    const int tid = threadIdx.x, wid = tid >> 5, lid = tid & 31;
    const int wm = wid & 3, wn = wid >> 2;

    const float*  Ab = A + ((size_t)b * Nn + i0) * Kk;
    const __half* Bb = g_W3VTh + ((size_t)b * Cc) * Kk;

    float4 ra[4];
    auto loadA = [&](int kt) {
#pragma unroll
        for (int it = 0; it < 4; it++) {
            const int idx = it * 256 + tid, row = idx >> 4, f4 = idx & 15;
            ra[it] = *(const float4*)(Ab + (size_t)row * Kk + kt * BKH + f4 * 4);
        }
    };
    auto stageA = [&](int st) {
#pragma unroll
        for (int it = 0; it < 4; it++) {
            const int idx = it * 256 + tid, row = idx >> 4, f4 = idx & 15;
            const uint32_t off = sw128((uint32_t)(row * 128 + f4 * 8));
            uint2 hv;
            hv.x = f22h2(ra[it].x, ra[it].y);
            hv.y = f22h2(ra[it].z, ra[it].w);
            *(uint2*)(smemRaw + st * 8192 + off) = hv;
        }
    };
    auto issueB = [&](int kt, int st) {
#pragma unroll
        for (int it = 0; it < 2; it++) {
            const int idx = it * 256 + tid, row = idx >> 3, seg = idx & 7;
            CP16(sBu[st] + sw128((uint32_t)(row * 128 + seg * 16)),
                 Bb + (size_t)row * Kk + kt * BKH + seg * 8);
        }
    };

    const uint32_t lrow = (uint32_t)((lid & 7) + ((lid >> 3) & 1) * 8);
    const uint32_t lkof = (uint32_t)((lid >> 4) * 16);
    const uint32_t aOff = (wm * 16 + lrow) * 128 + lkof;
    uint32_t bOff[2];
#pragma unroll
    for (int h = 0; h < 2; h++)
        bOff[h] = (wn * 32 + h * 16 + lrow) * 128 + lkof;

    float acc[4][4];
#pragma unroll
    for (int nt = 0; nt < 4; nt++)
#pragma unroll
        for (int e = 0; e < 4; e++) acc[nt][e] = 0.f;
    float2 dacc[2];
    dacc[0].x = dacc[0].y = dacc[1].x = dacc[1].y = 0.f;

    loadA(t0);
    issueB(t0, 0); CPCOMMIT();
    if (nkt > 1) issueB(t0 + 1, 1);
    CPCOMMIT();

    for (int qq = 0; qq < nkt; qq++) {
        const int st = qq & 1;
        stageA(st);
        if (qq + 1 < nkt) loadA(t0 + qq + 1);
        CPWAIT(1);
        __syncthreads();

#pragma unroll
        for (int ks = 0; ks < 4; ks++) {
            uint32_t af[4], bf[2][4];
            {
                uint32_t o = aOff + ks * 32;
                LDSM_X4(af, sAu[st] + (o ^ ((o >> 3) & 0x70)));
            }
#pragma unroll
            for (int h = 0; h < 2; h++) {
                uint32_t o = bOff[h] + ks * 32;
                LDSM_X4(bf[h], sBu[st] + (o ^ ((o >> 3) & 0x70)));
            }
            if (wn == 0) {   // deg: fp16 pair has k&3 = 2*(lid&1) + {0,1}
#pragma unroll
                for (int r = 0; r < 4; r++) {
                    const __half2 h = *(__half2*)&af[r];
                    const float2 f = __half22float2(h);
                    dacc[r & 1].x += f.x;
                    dacc[r & 1].y += f.y;
                }
            }
#pragma unroll
            for (int nt = 0; nt < 4; nt++)
                MMA_F16(acc[nt], af, bf[nt >> 1][nt & 1], bf[nt >> 1][(nt & 1) + 2]);
        }
        __syncthreads();
        if (qq + 2 < nkt) issueB(t0 + qq + 2, st);
        CPCOMMIT();
    }

    // deg: combine lanes l and l^2, atomically add to g_deg
    if (wn == 0) {
#pragma unroll
        for (int rh = 0; rh < 2; rh++) {
            float sx = dacc[rh].x + __shfl_xor_sync(0xFFFFFFFFu, dacc[rh].x, 2);
            float sy = dacc[rh].y + __shfl_xor_sync(0xFFFFFFFFu, dacc[rh].y, 2);
            if ((lid & 2) == 0) {
                const int row = wm * 16 + rh * 8 + (lid >> 2);
                const int e0 = 2 * (lid & 1);
                RED2(g_deg + ((size_t)b * Nn + i0 + row) * Ll + e0, sx, sy);
            }
        }
    }

    // term3: atomically subtract from g_accum (L2-resident target)
    const int gid = lid >> 2, tig = lid & 3;
    float* accp = g_accum + ((size_t)b * Nn + i0) * Cc;
#pragma unroll
    for (int nt = 0; nt < 4; nt++) {
        const int r0 = wm * 16 + gid;
        const int cc = wn * 32 + nt * 8 + 2 * tig;
        RED2(accp + (size_t)r0 * Cc + cc,       -acc[nt][0], -acc[nt][1]);
        RED2(accp + (size_t)(r0 + 8) * Cc + cc, -acc[nt][2], -acc[nt][3]);
    }

    // ---- fused split-K finisher: last-arriving split finalizes this tile ----
    __threadfence();                       // release: make our reds visible
    __syncthreads();                       // all threads' reds+fence done
    if (tid == 0)
        sLast = (atomicAdd(&g_cnt[b * 32 + mtb], 1u) == SPLITK - 1) ? 1u : 0u;
    __syncthreads();
    if (sLast) {
        __threadfence();                   // acquire side
#pragma unroll
        for (int it = 0; it < 16; it++) {
            const int idx = it * 256 + tid;
            const int rloc = idx >> 6, c = idx & 63;
            const size_t row = (size_t)b * Nn + i0 + rloc;
            const float4 dvv = __ldcg((const float4*)(g_deg + row * Ll));
            const float* w2vp = g_W2V + row * 256;
            const float x = __ldcg(g_accum + row * 64 + c)
                          + dvv.x * w2vp[c]       + dvv.y * w2vp[64 + c]
                          + dvv.z * w2vp[128 + c] + dvv.w * w2vp[192 + c];
            out[row * 64 + c] = 1.f / (1.f + expf(-x));
        }
    }
}

// ---------------- launch ----------------
extern "C" void kernel_launch(void* const* d_in, const int* in_sizes, int n_in,
                              void* d_out, int out_size) {
    const float* V  = (const float*)d_in[0];
    const float* A  = (const float*)d_in[1];
    const float* w1 = (const float*)d_in[2];
    const float* w2 = (const float*)d_in[3];
    const float* w3 = (const float*)d_in[4];
    float* out = (float*)d_out;

    pregemm_kernel<<<dim3(32, 9), 256>>>(V, w1, w2, w3);
    gemm_kernel<<<dim3(Nn / BM, Bdim, SPLITK), 256>>>(A, out);
}

// round 12
// speedup vs baseline: 1.1925x; 1.1925x over previous
#include <cuda_runtime.h>
#include <cuda_fp16.h>
#include <cstdint>
#include <math.h>

// ---------------- problem constants ----------------
#define Bdim 2
#define Nn   2048
#define Ff   64
#define Cc   64
#define Ll   4
#define Kk   (Nn*Ll)            // 8192
#define BM 64                   // rows per block (4 CTA/SM)
#define BKH 64                  // fp16 k-elements per tile (128 B rows)
#define NKTILES (Kk/BKH)        // 128
#define SPLITK 9                // 32 mtiles*2*9 = 576 blocks = 1 wave @ 4 CTA/SM

// ---------------- scratch (static device globals) ----------------
__device__ __align__(16) __half g_W3VTh[(size_t)Bdim*Cc*Kk];     // [b][c][k] fp16
__device__ __align__(16) float g_W2V [(size_t)Bdim*Nn*Ll*Cc];    // [m][l*64+c]
__device__ __align__(16) float g_accum[(size_t)Bdim*Nn*Cc];      // T1 - term3 (atomic)
__device__ __align__(16) float g_deg [(size_t)Bdim*Nn*Ll];       // deg (atomic)

// ---------------- helpers ----------------
__device__ __forceinline__ uint32_t smem_u32(const void* p) {
    uint32_t a;
    asm("{ .reg .u64 t; cvta.to.shared.u64 t, %1; cvt.u32.u64 %0, t; }" : "=r"(a) : "l"(p));
    return a;
}
__device__ __forceinline__ float to_tf32(float x) {
    uint32_t u;
    asm("cvt.rna.tf32.f32 %0, %1;" : "=r"(u) : "f"(x));
    return __uint_as_float(u);
}
__device__ __forceinline__ uint32_t sw128(uint32_t off) { return off ^ ((off >> 3) & 0x70); }
__device__ __forceinline__ uint32_t f22h2(float x, float y) {
    __half2 h = __floats2half2_rn(x, y);
    return *(uint32_t*)&h;
}

#define CP16(dst, src) \
    asm volatile("cp.async.cg.shared.global [%0], [%1], 16;" \
        :: "r"(dst), "l"(__cvta_generic_to_global(src)) : "memory")
#define CPCOMMIT() asm volatile("cp.async.commit_group;" ::: "memory")
#define CPWAIT(n)  asm volatile("cp.async.wait_group %0;" :: "n"(n) : "memory")

#define RED2(addr, x, y) \
    asm volatile("red.global.add.v2.f32 [%0], {%1, %2};" \
        :: "l"(addr), "f"(x), "f"(y) : "memory")

#define LDSM_X4(r, addr)                                                         \
    asm volatile("ldmatrix.sync.aligned.m8n8.x4.shared.b16 {%0,%1,%2,%3}, [%4];" \
        : "=r"((r)[0]), "=r"((r)[1]), "=r"((r)[2]), "=r"((r)[3]) : "r"(addr))

#define MMA_TF32(c, a, b0v, b1v)                                                 \
    asm volatile("mma.sync.aligned.m16n8k8.row.col.f32.tf32.tf32.f32 "           \
        "{%0,%1,%2,%3}, {%4,%5,%6,%7}, {%8,%9}, {%0,%1,%2,%3};"                  \
        : "+f"((c)[0]), "+f"((c)[1]), "+f"((c)[2]), "+f"((c)[3])                  \
        : "r"((a)[0]), "r"((a)[1]), "r"((a)[2]), "r"((a)[3]), "r"(b0v), "r"(b1v))

#define MMA_F16(c, a, b0v, b1v)                                                  \
    asm volatile("mma.sync.aligned.m16n8k16.row.col.f32.f16.f16.f32 "            \
        "{%0,%1,%2,%3}, {%4,%5,%6,%7}, {%8,%9}, {%0,%1,%2,%3};"                  \
        : "+f"((c)[0]), "+f"((c)[1]), "+f"((c)[2]), "+f"((c)[3])                  \
        : "r"((a)[0]), "r"((a)[1]), "r"((a)[2]), "r"((a)[3]), "r"(b0v), "r"(b1v))

// ---------------- precompute GEMM (tf32x3): [W3V | W2V | T1->accum] = V @ Wcat ----------------
// grid (32 M-tiles of 128 rows, 9 N-chunks), 256 threads.
// Weights loaded directly (transpose + tf32 split on the fly);
// nc==4 blocks also zero g_deg for this replay.
__global__ __launch_bounds__(256)
void pregemm_kernel(const float* __restrict__ V,
                    const float* __restrict__ w1,
                    const float* __restrict__ w2,
                    const float* __restrict__ w3) {
    __shared__ __align__(128) float sAhi[128 * 32];
    __shared__ __align__(128) float sAlo[128 * 32];
    __shared__ __align__(128) float sBhi[64 * 32];
    __shared__ __align__(128) float sBlo[64 * 32];
    const uint32_t aH = smem_u32(sAhi), aL = smem_u32(sAlo);
    const uint32_t bH = smem_u32(sBhi), bL = smem_u32(sBlo);

    const int mtile = blockIdx.x, nc = blockIdx.y;
    const int m0 = mtile * 128;
    const int tid = threadIdx.x, wid = tid >> 5, lid = tid & 31;
    const int wm = wid & 3, wn = wid >> 2;

    // per-replay scratch reset (kernel-boundary ordered before gemm)
    if (nc == 4) {
        float2 z; z.x = 0.f; z.y = 0.f;
        *(float2*)(g_deg + (size_t)mtile * 512 + tid * 2) = z;   // 32*512 = 16384
    }

    const float* Ab = V + (size_t)m0 * Ff;

    const int q = lid >> 3, rr = lid & 7;
    uint32_t aOff[2], bOff[2];
#pragma unroll
    for (int mt = 0; mt < 2; mt++)
        aOff[mt] = (uint32_t)((wm * 32 + mt * 16 + rr + (q & 1) * 8) * 128 + (q >> 1) * 16);
#pragma unroll
    for (int h = 0; h < 2; h++)
        bOff[h]  = (uint32_t)((wn * 32 + h * 16 + rr + (q >> 1) * 8) * 128 + (q & 1) * 16);

    float acc[2][4][4];
#pragma unroll
    for (int mt = 0; mt < 2; mt++)
#pragma unroll
        for (int nt = 0; nt < 4; nt++)
#pragma unroll
            for (int e = 0; e < 4; e++) acc[mt][nt][e] = 0.f;

    for (int kt = 0; kt < 2; kt++) {
        // stage A (hi/lo split)
#pragma unroll
        for (int it = 0; it < 4; it++) {
            const int idx = it * 256 + tid, row = idx >> 3, f4 = idx & 7;
            const float4 v = *(const float4*)(Ab + (size_t)row * Ff + kt * 32 + f4 * 4);
            float4 h, l;
            h.x = to_tf32(v.x); l.x = to_tf32(v.x - h.x);
            h.y = to_tf32(v.y); l.y = to_tf32(v.y - h.y);
            h.z = to_tf32(v.z); l.z = to_tf32(v.z - h.z);
            h.w = to_tf32(v.w); l.w = to_tf32(v.w - h.w);
            const uint32_t off = sw128((uint32_t)(row * 128 + f4 * 16));
            *(float4*)((char*)sAhi + off) = h;
            *(float4*)((char*)sAlo + off) = l;
        }
        // stage B: Wcat^T[nc*64+row][k] loaded directly from w1/w2/w3, split hi/lo
#pragma unroll
        for (int it = 0; it < 2; it++) {
            const int idx = it * 256 + tid, row = idx >> 3, f4 = idx & 7;
            const int t = nc * 64 + row;
            float4 v;
#pragma unroll
            for (int e = 0; e < 4; e++) {
                const int f = kt * 32 + f4 * 4 + e;
                float val;
                if (t < 256)      val = w3[((t >> 6) * Ff + f) * Cc + (t & 63)];
                else if (t < 512) val = w2[(((t - 256) >> 6) * Ff + f) * Cc + ((t - 256) & 63)];
                else              val = w1[f * Cc + (t - 512)];
                ((float*)&v)[e] = val;
            }
            float4 h, l;
            h.x = to_tf32(v.x); l.x = to_tf32(v.x - h.x);
            h.y = to_tf32(v.y); l.y = to_tf32(v.y - h.y);
            h.z = to_tf32(v.z); l.z = to_tf32(v.z - h.z);
            h.w = to_tf32(v.w); l.w = to_tf32(v.w - h.w);
            const uint32_t off = sw128((uint32_t)(row * 128 + f4 * 16));
            *(float4*)((char*)sBhi + off) = h;
            *(float4*)((char*)sBlo + off) = l;
        }
        __syncthreads();

#pragma unroll
        for (int ks = 0; ks < 4; ks++) {
            uint32_t afh[2][4], afl[2][4], bfh[2][4], bfl[2][4];
#pragma unroll
            for (int mt = 0; mt < 2; mt++) {
                uint32_t o = aOff[mt] + ks * 32, so = (o ^ ((o >> 3) & 0x70));
                LDSM_X4(afh[mt], aH + so);
                LDSM_X4(afl[mt], aL + so);
            }
#pragma unroll
            for (int h = 0; h < 2; h++) {
                uint32_t o = bOff[h] + ks * 32, so = (o ^ ((o >> 3) & 0x70));
                LDSM_X4(bfh[h], bH + so);
                LDSM_X4(bfl[h], bL + so);
            }
#pragma unroll
            for (int mt = 0; mt < 2; mt++)
#pragma unroll
                for (int nt = 0; nt < 4; nt++) {
                    const int hb = nt >> 1, eb = (nt & 1) * 2;
                    MMA_TF32(acc[mt][nt], afl[mt], bfh[hb][eb], bfh[hb][eb + 1]);
                    MMA_TF32(acc[mt][nt], afh[mt], bfl[hb][eb], bfl[hb][eb + 1]);
                    MMA_TF32(acc[mt][nt], afh[mt], bfh[hb][eb], bfh[hb][eb + 1]);
                }
        }
        __syncthreads();
    }

    const int gid = lid >> 2, tig = lid & 3;
#pragma unroll
    for (int mt = 0; mt < 2; mt++)
#pragma unroll
        for (int nt = 0; nt < 4; nt++)
#pragma unroll
            for (int e = 0; e < 4; e++) {
                const int row = wm * 32 + mt * 16 + gid + (e >> 1) * 8;
                const int col = wn * 32 + nt * 8 + 2 * tig + (e & 1);
                const int m = m0 + row;
                const float v = acc[mt][nt][e];
                if (nc < 4) {
                    const int bb = m >> 11, j = m & 2047;
                    g_W3VTh[((size_t)(bb * 64 + col)) * Kk + j * 4 + nc] = __float2half_rn(v);
                } else if (nc < 8) {
                    g_W2V[(size_t)m * 256 + (nc - 4) * 64 + col] = v;
                } else {
                    g_accum[(size_t)m * 64 + col] = v;   // T1 seeds the accumulator
                }
            }
}

// ---------------- main GEMM: fp16 m16n8k16, BM=64, split-K fused via L2 atomics ----------------
// grid (32, Bdim, SPLITK) = 576 blocks, 256 threads (8 warps).  (R10 structure: no fence/finisher)
__global__ __launch_bounds__(256, 4)
void gemm_kernel(const float* __restrict__ A) {
    __shared__ __align__(128) uint8_t smemRaw[32768];  // A:2x8KB, B:2x8KB
    const uint32_t sm = smem_u32(smemRaw);
    const uint32_t sAu[2] = { sm, sm + 8192 };
    const uint32_t sBu[2] = { sm + 16384, sm + 24576 };

    const int mtb = blockIdx.x, b = blockIdx.y, s = blockIdx.z;
    const int i0 = mtb * BM;
    const int t0 = (s * NKTILES) / SPLITK, t1 = ((s + 1) * NKTILES) / SPLITK;
    const int nkt = t1 - t0;
    const int tid = threadIdx.x, wid = tid >> 5, lid = tid & 31;
    const int wm = wid & 3, wn = wid >> 2;

    const float*  Ab = A + ((size_t)b * Nn + i0) * Kk;
    const __half* Bb = g_W3VTh + ((size_t)b * Cc) * Kk;

    float4 ra[4];
    auto loadA = [&](int kt) {
#pragma unroll
        for (int it = 0; it < 4; it++) {
            const int idx = it * 256 + tid, row = idx >> 4, f4 = idx & 15;
            ra[it] = *(const float4*)(Ab + (size_t)row * Kk + kt * BKH + f4 * 4);
        }
    };
    auto stageA = [&](int st) {
#pragma unroll
        for (int it = 0; it < 4; it++) {
            const int idx = it * 256 + tid, row = idx >> 4, f4 = idx & 15;
            const uint32_t off = sw128((uint32_t)(row * 128 + f4 * 8));
            uint2 hv;
            hv.x = f22h2(ra[it].x, ra[it].y);
            hv.y = f22h2(ra[it].z, ra[it].w);
            *(uint2*)(smemRaw + st * 8192 + off) = hv;
        }
    };
    auto issueB = [&](int kt, int st) {
#pragma unroll
        for (int it = 0; it < 2; it++) {
            const int idx = it * 256 + tid, row = idx >> 3, seg = idx & 7;
            CP16(sBu[st] + sw128((uint32_t)(row * 128 + seg * 16)),
                 Bb + (size_t)row * Kk + kt * BKH + seg * 8);
        }
    };

    const uint32_t lrow = (uint32_t)((lid & 7) + ((lid >> 3) & 1) * 8);
    const uint32_t lkof = (uint32_t)((lid >> 4) * 16);
    const uint32_t aOff = (wm * 16 + lrow) * 128 + lkof;
    uint32_t bOff[2];
#pragma unroll
    for (int h = 0; h < 2; h++)
        bOff[h] = (wn * 32 + h * 16 + lrow) * 128 + lkof;

    float acc[4][4];
#pragma unroll
    for (int nt = 0; nt < 4; nt++)
#pragma unroll
        for (int e = 0; e < 4; e++) acc[nt][e] = 0.f;
    float2 dacc[2];
    dacc[0].x = dacc[0].y = dacc[1].x = dacc[1].y = 0.f;

    loadA(t0);
    issueB(t0, 0); CPCOMMIT();
    if (nkt > 1) issueB(t0 + 1, 1);
    CPCOMMIT();

    for (int qq = 0; qq < nkt; qq++) {
        const int st = qq & 1;
        stageA(st);
        if (qq + 1 < nkt) loadA(t0 + qq + 1);
        CPWAIT(1);
        __syncthreads();

#pragma unroll
        for (int ks = 0; ks < 4; ks++) {
            uint32_t af[4], bf[2][4];
            {
                uint32_t o = aOff + ks * 32;
                LDSM_X4(af, sAu[st] + (o ^ ((o >> 3) & 0x70)));
            }
#pragma unroll
            for (int h = 0; h < 2; h++) {
                uint32_t o = bOff[h] + ks * 32;
                LDSM_X4(bf[h], sBu[st] + (o ^ ((o >> 3) & 0x70)));
            }
            if (wn == 0) {   // deg: fp16 pair has k&3 = 2*(lid&1) + {0,1}
#pragma unroll
                for (int r = 0; r < 4; r++) {
                    const __half2 h = *(__half2*)&af[r];
                    const float2 f = __half22float2(h);
                    dacc[r & 1].x += f.x;
                    dacc[r & 1].y += f.y;
                }
            }
#pragma unroll
            for (int nt = 0; nt < 4; nt++)
                MMA_F16(acc[nt], af, bf[nt >> 1][nt & 1], bf[nt >> 1][(nt & 1) + 2]);
        }
        __syncthreads();
        if (qq + 2 < nkt) issueB(t0 + qq + 2, st);
        CPCOMMIT();
    }

    // deg: combine lanes l and l^2, atomically add to g_deg
    if (wn == 0) {
#pragma unroll
        for (int rh = 0; rh < 2; rh++) {
            float sx = dacc[rh].x + __shfl_xor_sync(0xFFFFFFFFu, dacc[rh].x, 2);
            float sy = dacc[rh].y + __shfl_xor_sync(0xFFFFFFFFu, dacc[rh].y, 2);
            if ((lid & 2) == 0) {
                const int row = wm * 16 + rh * 8 + (lid >> 2);
                const int e0 = 2 * (lid & 1);
                RED2(g_deg + ((size_t)b * Nn + i0 + row) * Ll + e0, sx, sy);
            }
        }
    }

    // term3: atomically subtract from g_accum (L2-resident target)
    const int gid = lid >> 2, tig = lid & 3;
    float* accp = g_accum + ((size_t)b * Nn + i0) * Cc;
#pragma unroll
    for (int nt = 0; nt < 4; nt++) {
        const int r0 = wm * 16 + gid;
        const int cc = wn * 32 + nt * 8 + 2 * tig;
        RED2(accp + (size_t)r0 * Cc + cc,       -acc[nt][0], -acc[nt][1]);
        RED2(accp + (size_t)(r0 + 8) * Cc + cc, -acc[nt][2], -acc[nt][3]);
    }
}

// ---------------- epilogue: x = accum + deg.W2V, sigmoid ----------------
// grid (Nn/4, Bdim), 256 threads: 4 rows/block, 1 channel/thread.
__global__ __launch_bounds__(256)
void epilogue_kernel(float* __restrict__ out) {
    const int tid = threadIdx.x;
    const int c = tid & 63, r = tid >> 6;
    const int i = blockIdx.x * 4 + r, b = blockIdx.y;
    const size_t row = (size_t)b * Nn + i;

    const float4 dv = *(const float4*)(g_deg + row * Ll);
    const float* w2v = g_W2V + row * (Ll * Cc);
    const float x = g_accum[row * Cc + c]
                  + dv.x * w2v[0 * Cc + c] + dv.y * w2v[1 * Cc + c]
                  + dv.z * w2v[2 * Cc + c] + dv.w * w2v[3 * Cc + c];
    out[row * Cc + c] = 1.f / (1.f + expf(-x));
}

// ---------------- launch ----------------
extern "C" void kernel_launch(void* const* d_in, const int* in_sizes, int n_in,
                              void* d_out, int out_size) {
    const float* V  = (const float*)d_in[0];
    const float* A  = (const float*)d_in[1];
    const float* w1 = (const float*)d_in[2];
    const float* w2 = (const float*)d_in[3];
    const float* w3 = (const float*)d_in[4];
    float* out = (float*)d_out;

    pregemm_kernel<<<dim3(32, 9), 256>>>(V, w1, w2, w3);
    gemm_kernel<<<dim3(Nn / BM, Bdim, SPLITK), 256>>>(A);
    epilogue_kernel<<<dim3(Nn / 4, Bdim), 256>>>(out);
}

// round 13
// speedup vs baseline: 1.1994x; 1.0058x over previous
#include <cuda_runtime.h>
#include <cuda_fp16.h>
#include <cstdint>
#include <math.h>

// ---------------- problem constants ----------------
#define Bdim 2
#define Nn   2048
#define Ff   64
#define Cc   64
#define Ll   4
#define Kk   (Nn*Ll)            // 8192
#define BM 64                   // rows per block (4 CTA/SM)
#define BKH 64                  // fp16 k-elements per tile (128 B rows)
#define NKTILES (Kk/BKH)        // 128
#define SPLITK 9                // 32 mtiles*2*9 = 576 blocks = 1 wave @ 4 CTA/SM

// ---------------- scratch (static device globals) ----------------
__device__ __align__(16) __half g_W3VTh[(size_t)Bdim*Cc*Kk];     // [b][c][k] fp16
__device__ __align__(16) float g_W2V [(size_t)Bdim*Nn*Ll*Cc];    // [m][l*64+c]
__device__ __align__(16) float g_accum[(size_t)Bdim*Nn*Cc];      // T1 - term3 (atomic)
__device__ __align__(16) float g_deg [(size_t)Bdim*Nn*Ll];       // deg (atomic)

// ---------------- helpers ----------------
__device__ __forceinline__ uint32_t smem_u32(const void* p) {
    uint32_t a;
    asm("{ .reg .u64 t; cvta.to.shared.u64 t, %1; cvt.u32.u64 %0, t; }" : "=r"(a) : "l"(p));
    return a;
}
__device__ __forceinline__ uint32_t sw128(uint32_t off) { return off ^ ((off >> 3) & 0x70); }
__device__ __forceinline__ uint32_t f22h2(float x, float y) {
    __half2 h = __floats2half2_rn(x, y);
    return *(uint32_t*)&h;
}

#define CP16(dst, src) \
    asm volatile("cp.async.cg.shared.global [%0], [%1], 16;" \
        :: "r"(dst), "l"(__cvta_generic_to_global(src)) : "memory")
#define CPCOMMIT() asm volatile("cp.async.commit_group;" ::: "memory")
#define CPWAIT(n)  asm volatile("cp.async.wait_group %0;" :: "n"(n) : "memory")

#define RED2(addr, x, y) \
    asm volatile("red.global.add.v2.f32 [%0], {%1, %2};" \
        :: "l"(addr), "f"(x), "f"(y) : "memory")

#define LDSM_X4(r, addr)                                                         \
    asm volatile("ldmatrix.sync.aligned.m8n8.x4.shared.b16 {%0,%1,%2,%3}, [%4];" \
        : "=r"((r)[0]), "=r"((r)[1]), "=r"((r)[2]), "=r"((r)[3]) : "r"(addr))

#define MMA_F16(c, a, b0v, b1v)                                                  \
    asm volatile("mma.sync.aligned.m16n8k16.row.col.f32.f16.f16.f32 "            \
        "{%0,%1,%2,%3}, {%4,%5,%6,%7}, {%8,%9}, {%0,%1,%2,%3};"                  \
        : "+f"((c)[0]), "+f"((c)[1]), "+f"((c)[2]), "+f"((c)[3])                  \
        : "r"((a)[0]), "r"((a)[1]), "r"((a)[2]), "r"((a)[3]), "r"(b0v), "r"(b1v))

// ---------------- precompute GEMM (fp16x3 split): [W3V | W2V | T1->accum] = V @ Wcat ----------------
// grid (64 M-tiles of 64 rows, 9 N-chunks), 256 threads, single k-stage (K=64).
// v = hi(fp16) + lo(fp16); D = lo.hi + hi.lo + hi.hi (fp32 accum), rel err ~2^-22.
// Weights gathered/transposed/split on the fly. nc==4 blocks zero g_deg.
__global__ __launch_bounds__(256, 3)
void pregemm_kernel(const float* __restrict__ V,
                    const float* __restrict__ w1,
                    const float* __restrict__ w2,
                    const float* __restrict__ w3) {
    __shared__ __align__(128) uint8_t sA[16384];   // Ahi @0, Alo @8192
    __shared__ __align__(128) uint8_t sB[16384];   // Bhi @0, Blo @8192
    const uint32_t aH = smem_u32(sA), aL = aH + 8192;
    const uint32_t bH = smem_u32(sB), bL = bH + 8192;

    const int mtile = blockIdx.x, nc = blockIdx.y;
    const int m0 = mtile * 64;
    const int tid = threadIdx.x, wid = tid >> 5, lid = tid & 31;
    const int wm = wid & 3, wn = wid >> 2;

    // per-replay scratch reset (kernel-boundary ordered before gemm)
    if (nc == 4) g_deg[(size_t)mtile * 256 + tid] = 0.f;   // 64*256 = 16384

    // ---- stage A: 64x64 fp32 -> fp16 hi/lo, SW128 ----
#pragma unroll
    for (int it = 0; it < 4; it++) {
        const int idx = it * 256 + tid, row = idx >> 4, f4 = idx & 15;
        const float4 v = *(const float4*)(V + ((size_t)(m0 + row)) * Ff + f4 * 4);
        const __half hx = __float2half_rn(v.x), hy = __float2half_rn(v.y);
        const __half hz = __float2half_rn(v.z), hw = __float2half_rn(v.w);
        uint2 hv, lv;
        hv.x = f22h2(__half2float(hx), __half2float(hy));
        hv.y = f22h2(__half2float(hz), __half2float(hw));
        lv.x = f22h2(v.x - __half2float(hx), v.y - __half2float(hy));
        lv.y = f22h2(v.z - __half2float(hz), v.w - __half2float(hw));
        const uint32_t off = sw128((uint32_t)(row * 128 + f4 * 8));
        *(uint2*)(sA + off)        = hv;
        *(uint2*)(sA + 8192 + off) = lv;
    }
    // ---- stage B: gather Wcat^T[nc*64+row][f], split hi/lo ----
#pragma unroll
    for (int it = 0; it < 4; it++) {
        const int idx = it * 256 + tid, row = idx >> 4, f4 = idx & 15;
        const int t = nc * 64 + row;
        float v[4];
#pragma unroll
        for (int e = 0; e < 4; e++) {
            const int f = f4 * 4 + e;
            if (t < 256)      v[e] = w3[((t >> 6) * Ff + f) * Cc + (t & 63)];
            else if (t < 512) v[e] = w2[(((t - 256) >> 6) * Ff + f) * Cc + ((t - 256) & 63)];
            else              v[e] = w1[f * Cc + (t - 512)];
        }
        const __half hx = __float2half_rn(v[0]), hy = __float2half_rn(v[1]);
        const __half hz = __float2half_rn(v[2]), hw = __float2half_rn(v[3]);
        uint2 hv, lv;
        hv.x = f22h2(__half2float(hx), __half2float(hy));
        hv.y = f22h2(__half2float(hz), __half2float(hw));
        lv.x = f22h2(v[0] - __half2float(hx), v[1] - __half2float(hy));
        lv.y = f22h2(v[2] - __half2float(hz), v[3] - __half2float(hw));
        const uint32_t off = sw128((uint32_t)(row * 128 + f4 * 8));
        *(uint2*)(sB + off)        = hv;
        *(uint2*)(sB + 8192 + off) = lv;
    }
    __syncthreads();

    // ---- fragments + MMA (layout identical to proven gemm path) ----
    const uint32_t lrow = (uint32_t)((lid & 7) + ((lid >> 3) & 1) * 8);
    const uint32_t lkof = (uint32_t)((lid >> 4) * 16);
    const uint32_t aOff = (wm * 16 + lrow) * 128 + lkof;
    uint32_t bOff[2];
#pragma unroll
    for (int h = 0; h < 2; h++)
        bOff[h] = (wn * 32 + h * 16 + lrow) * 128 + lkof;

    float acc[4][4];
#pragma unroll
    for (int nt = 0; nt < 4; nt++)
#pragma unroll
        for (int e = 0; e < 4; e++) acc[nt][e] = 0.f;

#pragma unroll
    for (int ks = 0; ks < 4; ks++) {
        uint32_t afh[4], afl[4], bfh[2][4], bfl[2][4];
        {
            uint32_t o = aOff + ks * 32, so = (o ^ ((o >> 3) & 0x70));
            LDSM_X4(afh, aH + so);
            LDSM_X4(afl, aL + so);
        }
#pragma unroll
        for (int h = 0; h < 2; h++) {
            uint32_t o = bOff[h] + ks * 32, so = (o ^ ((o >> 3) & 0x70));
            LDSM_X4(bfh[h], bH + so);
            LDSM_X4(bfl[h], bL + so);
        }
#pragma unroll
        for (int nt = 0; nt < 4; nt++) {
            const int hb = nt >> 1, eb = nt & 1;
            MMA_F16(acc[nt], afl, bfh[hb][eb], bfh[hb][eb + 2]);
            MMA_F16(acc[nt], afh, bfl[hb][eb], bfl[hb][eb + 2]);
            MMA_F16(acc[nt], afh, bfh[hb][eb], bfh[hb][eb + 2]);
        }
    }

    // ---- route outputs by N-chunk ----
    const int gid = lid >> 2, tig = lid & 3;
#pragma unroll
    for (int nt = 0; nt < 4; nt++)
#pragma unroll
        for (int e = 0; e < 4; e++) {
            const int row = wm * 16 + (e >> 1) * 8 + gid;
            const int col = wn * 32 + nt * 8 + 2 * tig + (e & 1);
            const int m = m0 + row;
            const float v = acc[nt][e];
            if (nc < 4) {
                const int bb = m >> 11, j = m & 2047;
                g_W3VTh[((size_t)(bb * 64 + col)) * Kk + j * 4 + nc] = __float2half_rn(v);
            } else if (nc < 8) {
                g_W2V[(size_t)m * 256 + (nc - 4) * 64 + col] = v;
            } else {
                g_accum[(size_t)m * 64 + col] = v;   // T1 seeds the accumulator
            }
        }
}

// ---------------- main GEMM: fp16 m16n8k16, BM=64, split-K fused via L2 atomics ----------------
// grid (32, Bdim, SPLITK) = 576 blocks, 256 threads (8 warps).  (unchanged from R12)
__global__ __launch_bounds__(256, 4)
void gemm_kernel(const float* __restrict__ A) {
    __shared__ __align__(128) uint8_t smemRaw[32768];  // A:2x8KB, B:2x8KB
    const uint32_t sm = smem_u32(smemRaw);
    const uint32_t sAu[2] = { sm, sm + 8192 };
    const uint32_t sBu[2] = { sm + 16384, sm + 24576 };

    const int mtb = blockIdx.x, b = blockIdx.y, s = blockIdx.z;
    const int i0 = mtb * BM;
    const int t0 = (s * NKTILES) / SPLITK, t1 = ((s + 1) * NKTILES) / SPLITK;
    const int nkt = t1 - t0;
    const int tid = threadIdx.x, wid = tid >> 5, lid = tid & 31;
    const int wm = wid & 3, wn = wid >> 2;

    const float*  Ab = A + ((size_t)b * Nn + i0) * Kk;
    const __half* Bb = g_W3VTh + ((size_t)b * Cc) * Kk;

    float4 ra[4];
    auto loadA = [&](int kt) {
#pragma unroll
        for (int it = 0; it < 4; it++) {
            const int idx = it * 256 + tid, row = idx >> 4, f4 = idx & 15;
            ra[it] = *(const float4*)(Ab + (size_t)row * Kk + kt * BKH + f4 * 4);
        }
    };
    auto stageA = [&](int st) {
#pragma unroll
        for (int it = 0; it < 4; it++) {
            const int idx = it * 256 + tid, row = idx >> 4, f4 = idx & 15;
            const uint32_t off = sw128((uint32_t)(row * 128 + f4 * 8));
            uint2 hv;
            hv.x = f22h2(ra[it].x, ra[it].y);
            hv.y = f22h2(ra[it].z, ra[it].w);
            *(uint2*)(smemRaw + st * 8192 + off) = hv;
        }
    };
    auto issueB = [&](int kt, int st) {
#pragma unroll
        for (int it = 0; it < 2; it++) {
            const int idx = it * 256 + tid, row = idx >> 3, seg = idx & 7;
            CP16(sBu[st] + sw128((uint32_t)(row * 128 + seg * 16)),
                 Bb + (size_t)row * Kk + kt * BKH + seg * 8);
        }
    };

    const uint32_t lrow = (uint32_t)((lid & 7) + ((lid >> 3) & 1) * 8);
    const uint32_t lkof = (uint32_t)((lid >> 4) * 16);
    const uint32_t aOff = (wm * 16 + lrow) * 128 + lkof;
    uint32_t bOff[2];
#pragma unroll
    for (int h = 0; h < 2; h++)
        bOff[h] = (wn * 32 + h * 16 + lrow) * 128 + lkof;

    float acc[4][4];
#pragma unroll
    for (int nt = 0; nt < 4; nt++)
#pragma unroll
        for (int e = 0; e < 4; e++) acc[nt][e] = 0.f;
    float2 dacc[2];
    dacc[0].x = dacc[0].y = dacc[1].x = dacc[1].y = 0.f;

    loadA(t0);
    issueB(t0, 0); CPCOMMIT();
    if (nkt > 1) issueB(t0 + 1, 1);
    CPCOMMIT();

    for (int qq = 0; qq < nkt; qq++) {
        const int st = qq & 1;
        stageA(st);
        if (qq + 1 < nkt) loadA(t0 + qq + 1);
        CPWAIT(1);
        __syncthreads();

#pragma unroll
        for (int ks = 0; ks < 4; ks++) {
            uint32_t af[4], bf[2][4];
            {
                uint32_t o = aOff + ks * 32;
                LDSM_X4(af, sAu[st] + (o ^ ((o >> 3) & 0x70)));
            }
#pragma unroll
            for (int h = 0; h < 2; h++) {
                uint32_t o = bOff[h] + ks * 32;
                LDSM_X4(bf[h], sBu[st] + (o ^ ((o >> 3) & 0x70)));
            }
            if (wn == 0) {   // deg: fp16 pair has k&3 = 2*(lid&1) + {0,1}
#pragma unroll
                for (int r = 0; r < 4; r++) {
                    const __half2 h = *(__half2*)&af[r];
                    const float2 f = __half22float2(h);
                    dacc[r & 1].x += f.x;
                    dacc[r & 1].y += f.y;
                }
            }
#pragma unroll
            for (int nt = 0; nt < 4; nt++)
                MMA_F16(acc[nt], af, bf[nt >> 1][nt & 1], bf[nt >> 1][(nt & 1) + 2]);
        }
        __syncthreads();
        if (qq + 2 < nkt) issueB(t0 + qq + 2, st);
        CPCOMMIT();
    }

    // deg: combine lanes l and l^2, atomically add to g_deg
    if (wn == 0) {
#pragma unroll
        for (int rh = 0; rh < 2; rh++) {
            float sx = dacc[rh].x + __shfl_xor_sync(0xFFFFFFFFu, dacc[rh].x, 2);
            float sy = dacc[rh].y + __shfl_xor_sync(0xFFFFFFFFu, dacc[rh].y, 2);
            if ((lid & 2) == 0) {
                const int row = wm * 16 + rh * 8 + (lid >> 2);
                const int e0 = 2 * (lid & 1);
                RED2(g_deg + ((size_t)b * Nn + i0 + row) * Ll + e0, sx, sy);
            }
        }
    }

    // term3: atomically subtract from g_accum (L2-resident target)
    const int gid = lid >> 2, tig = lid & 3;
    float* accp = g_accum + ((size_t)b * Nn + i0) * Cc;
#pragma unroll
    for (int nt = 0; nt < 4; nt++) {
        const int r0 = wm * 16 + gid;
        const int cc = wn * 32 + nt * 8 + 2 * tig;
        RED2(accp + (size_t)r0 * Cc + cc,       -acc[nt][0], -acc[nt][1]);
        RED2(accp + (size_t)(r0 + 8) * Cc + cc, -acc[nt][2], -acc[nt][3]);
    }
}

// ---------------- epilogue: x = accum + deg.W2V, sigmoid ----------------
// grid (Nn/4, Bdim), 256 threads: 4 rows/block, 1 channel/thread. (unchanged)
__global__ __launch_bounds__(256)
void epilogue_kernel(float* __restrict__ out) {
    const int tid = threadIdx.x;
    const int c = tid & 63, r = tid >> 6;
    const int i = blockIdx.x * 4 + r, b = blockIdx.y;
    const size_t row = (size_t)b * Nn + i;

    const float4 dv = *(const float4*)(g_deg + row * Ll);
    const float* w2v = g_W2V + row * (Ll * Cc);
    const float x = g_accum[row * Cc + c]
                  + dv.x * w2v[0 * Cc + c] + dv.y * w2v[1 * Cc + c]
                  + dv.z * w2v[2 * Cc + c] + dv.w * w2v[3 * Cc + c];
    out[row * Cc + c] = 1.f / (1.f + expf(-x));
}

// ---------------- launch ----------------
extern "C" void kernel_launch(void* const* d_in, const int* in_sizes, int n_in,
                              void* d_out, int out_size) {
    const float* V  = (const float*)d_in[0];
    const float* A  = (const float*)d_in[1];
    const float* w1 = (const float*)d_in[2];
    const float* w2 = (const float*)d_in[3];
    const float* w3 = (const float*)d_in[4];
    float* out = (float*)d_out;

    pregemm_kernel<<<dim3(64, 9), 256>>>(V, w1, w2, w3);
    gemm_kernel<<<dim3(Nn / BM, Bdim, SPLITK), 256>>>(A);
    epilogue_kernel<<<dim3(Nn / 4, Bdim), 256>>>(out);
}

// round 14
// speedup vs baseline: 1.2930x; 1.0781x over previous
#include <cuda_runtime.h>
#include <cuda_fp16.h>
#include <cstdint>
#include <math.h>

// ---------------- problem constants ----------------
#define Bdim 2
#define Nn   2048
#define Ff   64
#define Cc   64
#define Ll   4
#define Kk   (Nn*Ll)            // 8192
#define BM 64                   // rows per block (4 CTA/SM)
#define BKH 64                  // fp16 k-elements per tile (128 B rows)
#define NKTILES (Kk/BKH)        // 128
#define SPLITK 9                // 32 mtiles*2*9 = 576 blocks = 1 wave @ 4 CTA/SM

// ---------------- scratch (static device globals) ----------------
__device__ __align__(16) __half g_W3VTh[(size_t)Bdim*Cc*Kk];     // [b][c][k] fp16
__device__ __align__(16) float g_W2V [(size_t)Bdim*Nn*Ll*Cc];    // [m][l*64+c]
__device__ __align__(16) float g_accum[(size_t)Bdim*Nn*Cc];      // T1 - term3 (atomic)
__device__ __align__(16) float g_deg [(size_t)Bdim*Nn*Ll];       // deg (atomic)
__device__ __align__(16) __half g_WTh16[576*Ff];                 // Wcat^T hi fp16
__device__ __align__(16) __half g_WTl16[576*Ff];                 // Wcat^T lo fp16
__device__ __align__(16) __half g_Vh[(size_t)Bdim*Nn*Ff];        // V hi fp16
__device__ __align__(16) __half g_Vl[(size_t)Bdim*Nn*Ff];        // V lo fp16

// ---------------- helpers ----------------
__device__ __forceinline__ uint32_t smem_u32(const void* p) {
    uint32_t a;
    asm("{ .reg .u64 t; cvta.to.shared.u64 t, %1; cvt.u32.u64 %0, t; }" : "=r"(a) : "l"(p));
    return a;
}
__device__ __forceinline__ uint32_t sw128(uint32_t off) { return off ^ ((off >> 3) & 0x70); }
__device__ __forceinline__ uint32_t f22h2(float x, float y) {
    __half2 h = __floats2half2_rn(x, y);
    return *(uint32_t*)&h;
}

#define CP16(dst, src) \
    asm volatile("cp.async.cg.shared.global [%0], [%1], 16;" \
        :: "r"(dst), "l"(__cvta_generic_to_global(src)) : "memory")
#define CPCOMMIT() asm volatile("cp.async.commit_group;" ::: "memory")
#define CPWAIT(n)  asm volatile("cp.async.wait_group %0;" :: "n"(n) : "memory")

#define RED2(addr, x, y) \
    asm volatile("red.global.add.v2.f32 [%0], {%1, %2};" \
        :: "l"(addr), "f"(x), "f"(y) : "memory")

#define LDSM_X4(r, addr)                                                         \
    asm volatile("ldmatrix.sync.aligned.m8n8.x4.shared.b16 {%0,%1,%2,%3}, [%4];" \
        : "=r"((r)[0]), "=r"((r)[1]), "=r"((r)[2]), "=r"((r)[3]) : "r"(addr))

#define MMA_F16(c, a, b0v, b1v)                                                  \
    asm volatile("mma.sync.aligned.m16n8k16.row.col.f32.f16.f16.f32 "            \
        "{%0,%1,%2,%3}, {%4,%5,%6,%7}, {%8,%9}, {%0,%1,%2,%3};"                  \
        : "+f"((c)[0]), "+f"((c)[1]), "+f"((c)[2]), "+f"((c)[3])                  \
        : "r"((a)[0]), "r"((a)[1]), "r"((a)[2]), "r"((a)[3]), "r"(b0v), "r"(b1v))

// ---------------- prep: coalesced transpose/split of weights + V, zero g_deg ----------------
// grid 1168 x 256. idx -> (row, f); rows 0..575 = Wcat^T, rows 576..4671 = V rows.
__global__ __launch_bounds__(256)
void prep_kernel(const float* __restrict__ V,
                 const float* __restrict__ w1,
                 const float* __restrict__ w2,
                 const float* __restrict__ w3) {
    const int idx = blockIdx.x * 256 + threadIdx.x;
    const int row = idx >> 6, f = idx & 63;
    float v;
    if (row < 256)      v = w3[((row >> 6) * Ff + f) * Cc + (row & 63)];
    else if (row < 512) v = w2[(((row - 256) >> 6) * Ff + f) * Cc + ((row - 256) & 63)];
    else if (row < 576) v = w1[f * Cc + (row - 512)];
    else                v = V[(size_t)(row - 576) * Ff + f];
    const __half h = __float2half_rn(v);
    const __half l = __float2half_rn(v - __half2float(h));
    if (row < 576) { g_WTh16[idx] = h; g_WTl16[idx] = l; }
    else {
        const size_t m = row - 576;
        g_Vh[m * Ff + f] = h; g_Vl[m * Ff + f] = l;
    }
    if (idx < Bdim * Nn * Ll) g_deg[idx] = 0.f;   // per-replay reset
}

// ---------------- precompute GEMM (fp16x3): [W3V | W2V | T1->accum] = V @ Wcat ----------------
// grid (64 M-tiles of 64 rows, 9 N-chunks), 256 threads, single k-stage, all cp.async.
__global__ __launch_bounds__(256, 3)
void pregemm_kernel() {
    __shared__ __align__(128) uint8_t sA[16384];   // Ahi @0, Alo @8192
    __shared__ __align__(128) uint8_t sB[16384];   // Bhi @0, Blo @8192
    const uint32_t aH = smem_u32(sA), aL = aH + 8192;
    const uint32_t bH = smem_u32(sB), bL = bH + 8192;

    const int mtile = blockIdx.x, nc = blockIdx.y;
    const int m0 = mtile * 64;
    const int tid = threadIdx.x, wid = tid >> 5, lid = tid & 31;
    const int wm = wid & 3, wn = wid >> 2;

    // stage all four 8KB tiles via cp.async (rows = 128B fp16, SW128)
    {
        const __half* srcAh = g_Vh    + (size_t)m0 * Ff;
        const __half* srcAl = g_Vl    + (size_t)m0 * Ff;
        const __half* srcBh = g_WTh16 + (size_t)nc * 64 * Ff;
        const __half* srcBl = g_WTl16 + (size_t)nc * 64 * Ff;
#pragma unroll
        for (int it = 0; it < 2; it++) {
            const int idx = it * 256 + tid, row = idx >> 3, seg = idx & 7;
            const uint32_t off = sw128((uint32_t)(row * 128 + seg * 16));
            const size_t so = (size_t)row * Ff + seg * 8;
            CP16(aH + off, srcAh + so);
            CP16(aL + off, srcAl + so);
            CP16(bH + off, srcBh + so);
            CP16(bL + off, srcBl + so);
        }
    }
    CPCOMMIT(); CPWAIT(0);
    __syncthreads();

    // fragments + MMA (identical to proven fp16 path)
    const uint32_t lrow = (uint32_t)((lid & 7) + ((lid >> 3) & 1) * 8);
    const uint32_t lkof = (uint32_t)((lid >> 4) * 16);
    const uint32_t aOff = (wm * 16 + lrow) * 128 + lkof;
    uint32_t bOff[2];
#pragma unroll
    for (int h = 0; h < 2; h++)
        bOff[h] = (wn * 32 + h * 16 + lrow) * 128 + lkof;

    float acc[4][4];
#pragma unroll
    for (int nt = 0; nt < 4; nt++)
#pragma unroll
        for (int e = 0; e < 4; e++) acc[nt][e] = 0.f;

#pragma unroll
    for (int ks = 0; ks < 4; ks++) {
        uint32_t afh[4], afl[4], bfh[2][4], bfl[2][4];
        {
            uint32_t o = aOff + ks * 32, so = (o ^ ((o >> 3) & 0x70));
            LDSM_X4(afh, aH + so);
            LDSM_X4(afl, aL + so);
        }
#pragma unroll
        for (int h = 0; h < 2; h++) {
            uint32_t o = bOff[h] + ks * 32, so = (o ^ ((o >> 3) & 0x70));
            LDSM_X4(bfh[h], bH + so);
            LDSM_X4(bfl[h], bL + so);
        }
#pragma unroll
        for (int nt = 0; nt < 4; nt++) {
            const int hb = nt >> 1, eb = nt & 1;
            MMA_F16(acc[nt], afl, bfh[hb][eb], bfh[hb][eb + 2]);
            MMA_F16(acc[nt], afh, bfl[hb][eb], bfl[hb][eb + 2]);
            MMA_F16(acc[nt], afh, bfh[hb][eb], bfh[hb][eb + 2]);
        }
    }

    // route outputs by N-chunk
    const int gid = lid >> 2, tig = lid & 3;
#pragma unroll
    for (int nt = 0; nt < 4; nt++)
#pragma unroll
        for (int e = 0; e < 4; e++) {
            const int row = wm * 16 + (e >> 1) * 8 + gid;
            const int col = wn * 32 + nt * 8 + 2 * tig + (e & 1);
            const int m = m0 + row;
            const float v = acc[nt][e];
            if (nc < 4) {
                const int bb = m >> 11, j = m & 2047;
                g_W3VTh[((size_t)(bb * 64 + col)) * Kk + j * 4 + nc] = __float2half_rn(v);
            } else if (nc < 8) {
                g_W2V[(size_t)m * 256 + (nc - 4) * 64 + col] = v;
            } else {
                g_accum[(size_t)m * 64 + col] = v;   // T1 seeds the accumulator
            }
        }
}

// ---------------- main GEMM: fp16 m16n8k16, BM=64, split-K fused via L2 atomics ----------------
// grid (32, Bdim, SPLITK) = 576 blocks, 256 threads (8 warps).  (unchanged)
__global__ __launch_bounds__(256, 4)
void gemm_kernel(const float* __restrict__ A) {
    __shared__ __align__(128) uint8_t smemRaw[32768];  // A:2x8KB, B:2x8KB
    const uint32_t sm = smem_u32(smemRaw);
    const uint32_t sAu[2] = { sm, sm + 8192 };
    const uint32_t sBu[2] = { sm + 16384, sm + 24576 };

    const int mtb = blockIdx.x, b = blockIdx.y, s = blockIdx.z;
    const int i0 = mtb * BM;
    const int t0 = (s * NKTILES) / SPLITK, t1 = ((s + 1) * NKTILES) / SPLITK;
    const int nkt = t1 - t0;
    const int tid = threadIdx.x, wid = tid >> 5, lid = tid & 31;
    const int wm = wid & 3, wn = wid >> 2;

    const float*  Ab = A + ((size_t)b * Nn + i0) * Kk;
    const __half* Bb = g_W3VTh + ((size_t)b * Cc) * Kk;

    float4 ra[4];
    auto loadA = [&](int kt) {
#pragma unroll
        for (int it = 0; it < 4; it++) {
            const int idx = it * 256 + tid, row = idx >> 4, f4 = idx & 15;
            ra[it] = *(const float4*)(Ab + (size_t)row * Kk + kt * BKH + f4 * 4);
        }
    };
    auto stageA = [&](int st) {
#pragma unroll
        for (int it = 0; it < 4; it++) {
            const int idx = it * 256 + tid, row = idx >> 4, f4 = idx & 15;
            const uint32_t off = sw128((uint32_t)(row * 128 + f4 * 8));
            uint2 hv;
            hv.x = f22h2(ra[it].x, ra[it].y);
            hv.y = f22h2(ra[it].z, ra[it].w);
            *(uint2*)(smemRaw + st * 8192 + off) = hv;
        }
    };
    auto issueB = [&](int kt, int st) {
#pragma unroll
        for (int it = 0; it < 2; it++) {
            const int idx = it * 256 + tid, row = idx >> 3, seg = idx & 7;
            CP16(sBu[st] + sw128((uint32_t)(row * 128 + seg * 16)),
                 Bb + (size_t)row * Kk + kt * BKH + seg * 8);
        }
    };

    const uint32_t lrow = (uint32_t)((lid & 7) + ((lid >> 3) & 1) * 8);
    const uint32_t lkof = (uint32_t)((lid >> 4) * 16);
    const uint32_t aOff = (wm * 16 + lrow) * 128 + lkof;
    uint32_t bOff[2];
#pragma unroll
    for (int h = 0; h < 2; h++)
        bOff[h] = (wn * 32 + h * 16 + lrow) * 128 + lkof;

    float acc[4][4];
#pragma unroll
    for (int nt = 0; nt < 4; nt++)
#pragma unroll
        for (int e = 0; e < 4; e++) acc[nt][e] = 0.f;
    float2 dacc[2];
    dacc[0].x = dacc[0].y = dacc[1].x = dacc[1].y = 0.f;

    loadA(t0);
    issueB(t0, 0); CPCOMMIT();
    if (nkt > 1) issueB(t0 + 1, 1);
    CPCOMMIT();

    for (int qq = 0; qq < nkt; qq++) {
        const int st = qq & 1;
        stageA(st);
        if (qq + 1 < nkt) loadA(t0 + qq + 1);
        CPWAIT(1);
        __syncthreads();

#pragma unroll
        for (int ks = 0; ks < 4; ks++) {
            uint32_t af[4], bf[2][4];
            {
                uint32_t o = aOff + ks * 32;
                LDSM_X4(af, sAu[st] + (o ^ ((o >> 3) & 0x70)));
            }
#pragma unroll
            for (int h = 0; h < 2; h++) {
                uint32_t o = bOff[h] + ks * 32;
                LDSM_X4(bf[h], sBu[st] + (o ^ ((o >> 3) & 0x70)));
            }
            if (wn == 0) {   // deg: fp16 pair has k&3 = 2*(lid&1) + {0,1}
#pragma unroll
                for (int r = 0; r < 4; r++) {
                    const __half2 h = *(__half2*)&af[r];
                    const float2 f = __half22float2(h);
                    dacc[r & 1].x += f.x;
                    dacc[r & 1].y += f.y;
                }
            }
#pragma unroll
            for (int nt = 0; nt < 4; nt++)
                MMA_F16(acc[nt], af, bf[nt >> 1][nt & 1], bf[nt >> 1][(nt & 1) + 2]);
        }
        __syncthreads();
        if (qq + 2 < nkt) issueB(t0 + qq + 2, st);
        CPCOMMIT();
    }

    // deg: combine lanes l and l^2, atomically add to g_deg
    if (wn == 0) {
#pragma unroll
        for (int rh = 0; rh < 2; rh++) {
            float sx = dacc[rh].x + __shfl_xor_sync(0xFFFFFFFFu, dacc[rh].x, 2);
            float sy = dacc[rh].y + __shfl_xor_sync(0xFFFFFFFFu, dacc[rh].y, 2);
            if ((lid & 2) == 0) {
                const int row = wm * 16 + rh * 8 + (lid >> 2);
                const int e0 = 2 * (lid & 1);
                RED2(g_deg + ((size_t)b * Nn + i0 + row) * Ll + e0, sx, sy);
            }
        }
    }

    // term3: atomically subtract from g_accum (L2-resident target)
    const int gid = lid >> 2, tig = lid & 3;
    float* accp = g_accum + ((size_t)b * Nn + i0) * Cc;
#pragma unroll
    for (int nt = 0; nt < 4; nt++) {
        const int r0 = wm * 16 + gid;
        const int cc = wn * 32 + nt * 8 + 2 * tig;
        RED2(accp + (size_t)r0 * Cc + cc,       -acc[nt][0], -acc[nt][1]);
        RED2(accp + (size_t)(r0 + 8) * Cc + cc, -acc[nt][2], -acc[nt][3]);
    }
}

// ---------------- epilogue: x = accum + deg.W2V, sigmoid ----------------
// grid (Nn/4, Bdim), 256 threads: 4 rows/block, 1 channel/thread. (unchanged)
__global__ __launch_bounds__(256)
void epilogue_kernel(float* __restrict__ out) {
    const int tid = threadIdx.x;
    const int c = tid & 63, r = tid >> 6;
    const int i = blockIdx.x * 4 + r, b = blockIdx.y;
    const size_t row = (size_t)b * Nn + i;

    const float4 dv = *(const float4*)(g_deg + row * Ll);
    const float* w2v = g_W2V + row * (Ll * Cc);
    const float x = g_accum[row * Cc + c]
                  + dv.x * w2v[0 * Cc + c] + dv.y * w2v[1 * Cc + c]
                  + dv.z * w2v[2 * Cc + c] + dv.w * w2v[3 * Cc + c];
    out[row * Cc + c] = 1.f / (1.f + expf(-x));
}

// ---------------- launch ----------------
extern "C" void kernel_launch(void* const* d_in, const int* in_sizes, int n_in,
                              void* d_out, int out_size) {
    const float* V  = (const float*)d_in[0];
    const float* A  = (const float*)d_in[1];
    const float* w1 = (const float*)d_in[2];
    const float* w2 = (const float*)d_in[3];
    const float* w3 = (const float*)d_in[4];
    float* out = (float*)d_out;

    prep_kernel<<<1168, 256>>>(V, w1, w2, w3);
    pregemm_kernel<<<dim3(64, 9), 256>>>();
    gemm_kernel<<<dim3(Nn / BM, Bdim, SPLITK), 256>>>(A);
    epilogue_kernel<<<dim3(Nn / 4, Bdim), 256>>>(out);
}